// round 13
// baseline (speedup 1.0000x reference)
#include <cuda_runtime.h>
#include <cuda_fp16.h>
#include <cstdint>

// ----------------------------------------------------------------------------
// GCN: agg1 = relu(Ahat (x@W1) + b1); h2 = agg1 @ W2;
//      pool = segment_max(relu(Ahat h2 + b2), batch); out = pool @ Wfc + bfc
// R13 (on R12 base): pre-converted weights (W1 -> tf32 bits once, W2 -> fp16
// transposed once) remove per-use cvt from both GEMM inner loops; gathers
// factor dnode out of the edge loop (1 fewer instr/edge/lane).
// Bucketed edges (no count/scan); cnt zeroed by k_dis, pool by k_fc.
// ----------------------------------------------------------------------------

#define N_NODES 50000
#define N_EDGES 800000
#define N_GRAPHS 128
#define IN_DIM 256
#define H1 128
#define H2 64
#define OUT_DIM 10
#define CAP 192

__device__ int    g_cnt[N_NODES];        // zero at load; re-zeroed by k_dis
__device__ int    g_deg[N_NODES];
__device__ float  g_dis[N_NODES];
__device__ int    g_crow[(size_t)N_NODES * CAP];
__device__ float  g_W1t[IN_DIM * H1];    // W1 rounded to tf32 bit-pattern
__device__ __half g_W2h[H2 * H1];        // W2 transposed [n][k], fp16
__device__ __half g_h1[(size_t)N_NODES * H1];
__device__ __half g_agg1[(size_t)N_NODES * H1];
__device__ __half g_h2[(size_t)N_NODES * H2];
__device__ float  g_pool[N_GRAPHS * H2]; // zero at load; re-zeroed by k_fc

// ---------------------------------------------------------------- utils
__device__ __forceinline__ uint32_t f2tf(float x) {
    uint32_t u;
    asm("cvt.rna.tf32.f32 %0, %1;" : "=r"(u) : "f"(x));
    return u;
}

#define MMA_TF32(d, a, b)                                                     \
    asm volatile(                                                             \
        "mma.sync.aligned.m16n8k8.row.col.f32.tf32.tf32.f32 "                 \
        "{%0,%1,%2,%3},{%4,%5,%6,%7},{%8,%9},{%0,%1,%2,%3};"                  \
        : "+f"((d)[0]), "+f"((d)[1]), "+f"((d)[2]), "+f"((d)[3])              \
        : "r"((a)[0]), "r"((a)[1]), "r"((a)[2]), "r"((a)[3]),                 \
          "r"((b)[0]), "r"((b)[1]))

#define MMA_F16(d, a, b)                                                      \
    asm volatile(                                                             \
        "mma.sync.aligned.m16n8k16.row.col.f32.f16.f16.f32 "                  \
        "{%0,%1,%2,%3},{%4,%5,%6,%7},{%8,%9},{%0,%1,%2,%3};"                  \
        : "+f"((d)[0]), "+f"((d)[1]), "+f"((d)[2]), "+f"((d)[3])              \
        : "r"((a)[0]), "r"((a)[1]), "r"((a)[2]), "r"((a)[3]),                 \
          "r"((b)[0]), "r"((b)[1]))

__device__ __forceinline__ void cp16(uint32_t saddr, const void* gaddr, int sz) {
    asm volatile("cp.async.cg.shared.global [%0], [%1], 16, %2;"
                 :: "r"(saddr), "l"(gaddr), "r"(sz));
}

__device__ __forceinline__ float4 ldh4(const __half* p) {
    uint2 u = *(const uint2*)p;
    float2 a = __half22float2(*(__half2*)&u.x);
    float2 b = __half22float2(*(__half2*)&u.y);
    return make_float4(a.x, a.y, b.x, b.y);
}

// ---------------------------------------------------------------- weight prep (once per launch)
__global__ void k_prepW(const float* __restrict__ W1, const float* __restrict__ W2,
                        float* __restrict__ W1t, __half* __restrict__ W2h)
{
    int i = blockIdx.x * blockDim.x + threadIdx.x;
    if (i < IN_DIM * H1)
        W1t[i] = __uint_as_float(f2tf(W1[i]));
    if (i < H1 * H2) {
        int k = i >> 6, n = i & 63;
        W2h[n * H1 + k] = __float2half(W2[i]);
    }
}

// ---------------------------------------------------------------- bucket fill
__global__ void k_fill(const int* __restrict__ row, const int* __restrict__ col,
                       int* __restrict__ cnt, int* __restrict__ crow)
{
    int i = blockIdx.x * blockDim.x + threadIdx.x;
    if (i * 4 >= N_EDGES) return;
    int4 r = *(const int4*)(row + i * 4);
    int4 c = *(const int4*)(col + i * 4);
    int p0 = atomicAdd(&cnt[c.x], 1);
    int p1 = atomicAdd(&cnt[c.y], 1);
    int p2 = atomicAdd(&cnt[c.z], 1);
    int p3 = atomicAdd(&cnt[c.w], 1);
    crow[(size_t)c.x * CAP + p0] = r.x;
    crow[(size_t)c.y * CAP + p1] = r.y;
    crow[(size_t)c.z * CAP + p2] = r.z;
    crow[(size_t)c.w * CAP + p3] = r.w;
}

__global__ void k_dis(int* __restrict__ cnt, int* __restrict__ deg,
                      float* __restrict__ dis)
{
    int i = blockIdx.x * blockDim.x + threadIdx.x;
    if (i < N_NODES) {
        int v = cnt[i];
        deg[i] = v;
        dis[i] = rsqrtf((float)(v + 1));
        cnt[i] = 0;
    }
}

// ---------------------------------------------------------------- GEMM1 (tf32, 3-stage cp.async, fp16 out)
// B (= W1t) is pre-rounded to tf32 bits: B-fragments skip cvt.
template<int BM, int BN, int BK, int WARPS, int WARPS_M, int WM, int WN>
__global__ void __launch_bounds__(WARPS * 32)
k_gemm_ca(const float* __restrict__ A, const float* __restrict__ B,
          __half* __restrict__ C, int M, int K)
{
    constexpr int MT = WM / 16, NT = WN / 8;
    constexpr int SA = BK + 4;
    constexpr int SB = BN + 8;
    extern __shared__ float dyn[];
    float* As = dyn;
    float* Bs = dyn + 3 * BM * SA;

    const int tid = threadIdx.x, wid = tid >> 5, lane = tid & 31;
    const int wm = wid % WARPS_M, wn = wid / WARPS_M;
    const int g = lane >> 2, tig = lane & 3;
    const int m0 = blockIdx.x * BM;

    float acc[MT][NT][4];
#pragma unroll
    for (int i = 0; i < MT; i++)
#pragma unroll
        for (int j = 0; j < NT; j++)
#pragma unroll
            for (int q = 0; q < 4; q++) acc[i][j][q] = 0.f;

    auto loadTiles = [&](int buf, int k0) {
        float* Ab = As + buf * BM * SA;
        float* Bb = Bs + buf * BK * SB;
#pragma unroll
        for (int i = tid; i < BM * BK / 4; i += WARPS * 32) {
            int r = i / (BK / 4), c4 = i % (BK / 4);
            cp16((uint32_t)__cvta_generic_to_shared(&Ab[r * SA + c4 * 4]),
                 A + (size_t)(m0 + r) * K + k0 + c4 * 4,
                 (m0 + r < M) ? 16 : 0);
        }
#pragma unroll
        for (int i = tid; i < BK * BN / 4; i += WARPS * 32) {
            int kk = i / (BN / 4), c4 = i % (BN / 4);
            cp16((uint32_t)__cvta_generic_to_shared(&Bb[kk * SB + c4 * 4]),
                 B + (size_t)(k0 + kk) * BN + c4 * 4, 16);
        }
        asm volatile("cp.async.commit_group;");
    };

    const int nk = K / BK;
    loadTiles(0, 0);
    loadTiles(1, BK);
    for (int t = 0; t < nk; t++) {
        if (t + 2 < nk) {
            loadTiles((t + 2) % 3, (t + 2) * BK);
            asm volatile("cp.async.wait_group 2;");
        } else if (t + 1 < nk) {
            asm volatile("cp.async.wait_group 1;");
        } else {
            asm volatile("cp.async.wait_group 0;");
        }
        __syncthreads();
        const int buf = t % 3;
        const float* Ab = As + buf * BM * SA;
        const float* Bb = Bs + buf * BK * SB;

#pragma unroll
        for (int kk = 0; kk < BK / 8; kk++) {
            uint32_t af[MT][4], bf[NT][2];
#pragma unroll
            for (int mt = 0; mt < MT; mt++) {
                int r = wm * WM + mt * 16;
                af[mt][0] = f2tf(Ab[(r + g)     * SA + kk * 8 + tig]);
                af[mt][1] = f2tf(Ab[(r + g + 8) * SA + kk * 8 + tig]);
                af[mt][2] = f2tf(Ab[(r + g)     * SA + kk * 8 + tig + 4]);
                af[mt][3] = f2tf(Ab[(r + g + 8) * SA + kk * 8 + tig + 4]);
            }
#pragma unroll
            for (int nt = 0; nt < NT; nt++) {
                int c = wn * WN + nt * 8;
                bf[nt][0] = __float_as_uint(Bb[(kk * 8 + tig)     * SB + c + g]);
                bf[nt][1] = __float_as_uint(Bb[(kk * 8 + tig + 4) * SB + c + g]);
            }
#pragma unroll
            for (int mt = 0; mt < MT; mt++)
#pragma unroll
                for (int nt = 0; nt < NT; nt++)
                    MMA_TF32(acc[mt][nt], af[mt], bf[nt]);
        }
        __syncthreads();
    }

#pragma unroll
    for (int mt = 0; mt < MT; mt++) {
        int r0 = m0 + wm * WM + mt * 16 + g;
#pragma unroll
        for (int nt = 0; nt < NT; nt++) {
            int c = wn * WN + nt * 8 + 2 * tig;
            if (r0 < M)
                *(__half2*)(C + (size_t)r0 * BN + c) =
                    __floats2half2_rn(acc[mt][nt][0], acc[mt][nt][1]);
            if (r0 + 8 < M)
                *(__half2*)(C + (size_t)(r0 + 8) * BN + c) =
                    __floats2half2_rn(acc[mt][nt][2], acc[mt][nt][3]);
        }
    }
}

#define G1_SMEM (3 * (128 * 20 + 16 * 136) * 4)

// ---------------------------------------------------------------- GEMM2 (fp16 mma; W2 pre-converted)
#define G2_SA 136
#define G2_SB 136
#define G2_SMEM ((128 * G2_SA + 64 * G2_SB) * 2)

__global__ void __launch_bounds__(256)
k_gemm2_f16(const __half* __restrict__ A, const __half* __restrict__ W2h,
            __half* __restrict__ C, int M)
{
    extern __shared__ __half sm[];
    __half* As  = sm;                     // [128][G2_SA]
    __half* Bs2 = sm + 128 * G2_SA;       // [64][G2_SB]  (n-major, k contiguous)

    const int tid = threadIdx.x, wid = tid >> 5, lane = tid & 31;
    const int wm = wid % 4, wn = wid / 4;
    const int g = lane >> 2, tig = lane & 3;
    const int m0 = blockIdx.x * 128;

#pragma unroll
    for (int i = tid; i < 128 * 16; i += 256) {
        int r = i / 16, c8 = i % 16;
        cp16((uint32_t)__cvta_generic_to_shared(&As[r * G2_SA + c8 * 8]),
             A + (size_t)(m0 + r) * 128 + c8 * 8,
             (m0 + r < M) ? 16 : 0);
    }
#pragma unroll
    for (int i = tid; i < 64 * 16; i += 256) {
        int n = i / 16, c8 = i % 16;
        cp16((uint32_t)__cvta_generic_to_shared(&Bs2[n * G2_SB + c8 * 8]),
             W2h + n * H1 + c8 * 8, 16);
    }
    asm volatile("cp.async.commit_group;");
    asm volatile("cp.async.wait_group 0;");
    __syncthreads();

    float acc[2][4][4];
#pragma unroll
    for (int i = 0; i < 2; i++)
#pragma unroll
        for (int j = 0; j < 4; j++)
#pragma unroll
            for (int q = 0; q < 4; q++) acc[i][j][q] = 0.f;

#pragma unroll
    for (int kk = 0; kk < 8; kk++) {
        uint32_t af[2][4], bf[4][2];
#pragma unroll
        for (int mt = 0; mt < 2; mt++) {
            int r = wm * 32 + mt * 16;
            af[mt][0] = *(const uint32_t*)&As[(r + g)     * G2_SA + kk * 16 + 2 * tig];
            af[mt][1] = *(const uint32_t*)&As[(r + g + 8) * G2_SA + kk * 16 + 2 * tig];
            af[mt][2] = *(const uint32_t*)&As[(r + g)     * G2_SA + kk * 16 + 8 + 2 * tig];
            af[mt][3] = *(const uint32_t*)&As[(r + g + 8) * G2_SA + kk * 16 + 8 + 2 * tig];
        }
#pragma unroll
        for (int nt = 0; nt < 4; nt++) {
            int c = wn * 32 + nt * 8;
            bf[nt][0] = *(const uint32_t*)&Bs2[(c + g) * G2_SB + kk * 16 + 2 * tig];
            bf[nt][1] = *(const uint32_t*)&Bs2[(c + g) * G2_SB + kk * 16 + 8 + 2 * tig];
        }
#pragma unroll
        for (int mt = 0; mt < 2; mt++)
#pragma unroll
            for (int nt = 0; nt < 4; nt++)
                MMA_F16(acc[mt][nt], af[mt], bf[nt]);
    }

#pragma unroll
    for (int mt = 0; mt < 2; mt++) {
        int r0 = m0 + wm * 32 + mt * 16 + g;
#pragma unroll
        for (int nt = 0; nt < 4; nt++) {
            int c = wn * 32 + nt * 8 + 2 * tig;
            if (r0 < M)
                *(__half2*)(C + (size_t)r0 * 64 + c) =
                    __floats2half2_rn(acc[mt][nt][0], acc[mt][nt][1]);
            if (r0 + 8 < M)
                *(__half2*)(C + (size_t)(r0 + 8) * 64 + c) =
                    __floats2half2_rn(acc[mt][nt][2], acc[mt][nt][3]);
        }
    }
}

// ---------------------------------------------------------------- gather1: acc = dnode*(self*dnode + sum dis[p]*v), +bias, relu
__global__ void k_gather128(const __half* __restrict__ h, __half* __restrict__ agg,
                            const int* __restrict__ deg, const int* __restrict__ crow,
                            const float* __restrict__ dis, const float* __restrict__ bias)
{
    int node = (blockIdx.x * blockDim.x + threadIdx.x) >> 5;
    int lane = threadIdx.x & 31;
    if (node >= N_NODES) return;

    float dnode = dis[node];
    float4 acc = ldh4(h + (size_t)node * 128 + lane * 4);
    acc.x *= dnode; acc.y *= dnode; acc.z *= dnode; acc.w *= dnode;

    const int* base = crow + (size_t)node * CAP;
    int e = deg[node];
    int j = 0;
    for (; j + 7 < e; j += 8) {
        int p[8];
#pragma unroll
        for (int q = 0; q < 8; q++) p[q] = __ldg(base + j + q);
        float4 v[8];
        float nn[8];
#pragma unroll
        for (int q = 0; q < 8; q++) {
            v[q] = ldh4(h + (size_t)p[q] * 128 + lane * 4);
            nn[q] = __ldg(&dis[p[q]]);
        }
#pragma unroll
        for (int q = 0; q < 8; q++) {
            acc.x = fmaf(v[q].x, nn[q], acc.x); acc.y = fmaf(v[q].y, nn[q], acc.y);
            acc.z = fmaf(v[q].z, nn[q], acc.z); acc.w = fmaf(v[q].w, nn[q], acc.w);
        }
    }
    for (; j + 3 < e; j += 4) {
        int p[4];
#pragma unroll
        for (int q = 0; q < 4; q++) p[q] = __ldg(base + j + q);
#pragma unroll
        for (int q = 0; q < 4; q++) {
            float4 v = ldh4(h + (size_t)p[q] * 128 + lane * 4);
            float n = __ldg(&dis[p[q]]);
            acc.x = fmaf(v.x, n, acc.x); acc.y = fmaf(v.y, n, acc.y);
            acc.z = fmaf(v.z, n, acc.z); acc.w = fmaf(v.w, n, acc.w);
        }
    }
    for (; j < e; j++) {
        int p = __ldg(base + j);
        float n = __ldg(&dis[p]);
        float4 v = ldh4(h + (size_t)p * 128 + lane * 4);
        acc.x = fmaf(v.x, n, acc.x); acc.y = fmaf(v.y, n, acc.y);
        acc.z = fmaf(v.z, n, acc.z); acc.w = fmaf(v.w, n, acc.w);
    }
    float4 bb = *(const float4*)(bias + lane * 4);
    acc.x = fmaxf(fmaf(acc.x, dnode, bb.x), 0.f);
    acc.y = fmaxf(fmaf(acc.y, dnode, bb.y), 0.f);
    acc.z = fmaxf(fmaf(acc.z, dnode, bb.z), 0.f);
    acc.w = fmaxf(fmaf(acc.w, dnode, bb.w), 0.f);
    uint2 st;
    *(__half2*)&st.x = __floats2half2_rn(acc.x, acc.y);
    *(__half2*)&st.y = __floats2half2_rn(acc.z, acc.w);
    *(uint2*)(agg + (size_t)node * 128 + lane * 4) = st;
}

// ---------------------------------------------------------------- gather2 + max-pool (dnode factored)
__global__ void k_gather64pool(const __half* __restrict__ h2,
                               const int* __restrict__ deg, const int* __restrict__ crow,
                               const float* __restrict__ dis, const float* __restrict__ b2,
                               const int* __restrict__ batch, float* __restrict__ pool)
{
    int node = (blockIdx.x * blockDim.x + threadIdx.x) >> 5;
    int lane = threadIdx.x & 31;
    if (node >= N_NODES) return;

    float dnode = dis[node];
    float2 acc = __half22float2(*(const __half2*)(h2 + (size_t)node * 64 + lane * 2));
    acc.x *= dnode; acc.y *= dnode;

    const int* base = crow + (size_t)node * CAP;
    int e = deg[node];
    int j = 0;
    for (; j + 7 < e; j += 8) {
        int p[8];
#pragma unroll
        for (int q = 0; q < 8; q++) p[q] = __ldg(base + j + q);
        float2 v[8];
        float nn[8];
#pragma unroll
        for (int q = 0; q < 8; q++) {
            v[q] = __half22float2(*(const __half2*)(h2 + (size_t)p[q] * 64 + lane * 2));
            nn[q] = __ldg(&dis[p[q]]);
        }
#pragma unroll
        for (int q = 0; q < 8; q++) {
            acc.x = fmaf(v[q].x, nn[q], acc.x); acc.y = fmaf(v[q].y, nn[q], acc.y);
        }
    }
    for (; j + 3 < e; j += 4) {
        int p[4];
#pragma unroll
        for (int q = 0; q < 4; q++) p[q] = __ldg(base + j + q);
#pragma unroll
        for (int q = 0; q < 4; q++) {
            float2 v = __half22float2(*(const __half2*)(h2 + (size_t)p[q] * 64 + lane * 2));
            float n = __ldg(&dis[p[q]]);
            acc.x = fmaf(v.x, n, acc.x); acc.y = fmaf(v.y, n, acc.y);
        }
    }
    for (; j < e; j++) {
        int p = __ldg(base + j);
        float n = __ldg(&dis[p]);
        float2 v = __half22float2(*(const __half2*)(h2 + (size_t)p * 64 + lane * 2));
        acc.x = fmaf(v.x, n, acc.x); acc.y = fmaf(v.y, n, acc.y);
    }
    float2 bb = *(const float2*)(b2 + lane * 2);
    acc.x = fmaxf(fmaf(acc.x, dnode, bb.x), 0.f);
    acc.y = fmaxf(fmaf(acc.y, dnode, bb.y), 0.f);

    int gph = batch[node];
    atomicMax((unsigned int*)&pool[gph * H2 + lane * 2],     __float_as_uint(acc.x));
    atomicMax((unsigned int*)&pool[gph * H2 + lane * 2 + 1], __float_as_uint(acc.y));
}

// ---------------------------------------------------------------- final FC (re-zeroes pool after use)
__global__ void k_fc(float* __restrict__ pool, const float* __restrict__ Wfc,
                     const float* __restrict__ bfc, float* __restrict__ out)
{
    __shared__ float w[H2 * OUT_DIM];
    __shared__ float bb[OUT_DIM];
    int tid = threadIdx.x;
    for (int i = tid; i < H2 * OUT_DIM; i += blockDim.x) w[i] = Wfc[i];
    if (tid < OUT_DIM) bb[tid] = bfc[tid];
    __syncthreads();
    if (tid < N_GRAPHS) {
        float acc[OUT_DIM];
#pragma unroll
        for (int j = 0; j < OUT_DIM; j++) acc[j] = bb[j];
        for (int k = 0; k < H2; k++) {
            float g = pool[tid * H2 + k];
#pragma unroll
            for (int j = 0; j < OUT_DIM; j++) acc[j] = fmaf(g, w[k * OUT_DIM + j], acc[j]);
        }
#pragma unroll
        for (int j = 0; j < OUT_DIM; j++) out[tid * OUT_DIM + j] = acc[j];
    }
    __syncthreads();
    for (int i = tid; i < N_GRAPHS * H2; i += blockDim.x) pool[i] = 0.f;
}

// ---------------------------------------------------------------- launch
extern "C" void kernel_launch(void* const* d_in, const int* in_sizes, int n_in,
                              void* d_out, int out_size)
{
    const float* x    = (const float*)d_in[0];
    const int*   ei   = (const int*)d_in[1];
    const int*   batch= (const int*)d_in[2];
    const float* W1   = (const float*)d_in[3];
    const float* b1   = (const float*)d_in[4];
    const float* W2   = (const float*)d_in[5];
    const float* b2   = (const float*)d_in[6];
    const float* Wfc  = (const float*)d_in[7];
    const float* bfc  = (const float*)d_in[8];
    float* out = (float*)d_out;

    const int* row = ei;
    const int* col = ei + N_EDGES;

    int *cnt, *deg, *crow;
    float *dis, *pool, *W1t;
    __half *h1, *agg1, *h2, *W2h;
    cudaGetSymbolAddress((void**)&cnt,  g_cnt);
    cudaGetSymbolAddress((void**)&deg,  g_deg);
    cudaGetSymbolAddress((void**)&dis,  g_dis);
    cudaGetSymbolAddress((void**)&crow, g_crow);
    cudaGetSymbolAddress((void**)&W1t,  g_W1t);
    cudaGetSymbolAddress((void**)&W2h,  g_W2h);
    cudaGetSymbolAddress((void**)&h1,   g_h1);
    cudaGetSymbolAddress((void**)&agg1, g_agg1);
    cudaGetSymbolAddress((void**)&h2,   g_h2);
    cudaGetSymbolAddress((void**)&pool, g_pool);

    cudaFuncSetAttribute((const void*)k_gemm_ca<128, 128, 16, 16, 4, 32, 32>,
                         cudaFuncAttributeMaxDynamicSharedMemorySize, G1_SMEM);
    cudaFuncSetAttribute(k_gemm2_f16,
                         cudaFuncAttributeMaxDynamicSharedMemorySize, G2_SMEM);

    cudaStream_t s2;
    cudaStreamCreateWithFlags(&s2, cudaStreamNonBlocking);
    cudaEvent_t evF, evJ;
    cudaEventCreateWithFlags(&evF, cudaEventDisableTiming);
    cudaEventCreateWithFlags(&evJ, cudaEventDisableTiming);

    // fork: bucket fill + dis on s2 (hidden under GEMM1)
    cudaEventRecord(evF, 0);
    cudaStreamWaitEvent(s2, evF, 0);
    k_fill<<<(N_EDGES / 4 + 255) / 256, 256, 0, s2>>>(row, col, cnt, crow);
    k_dis<<<(N_NODES + 255) / 256, 256, 0, s2>>>(cnt, deg, dis);
    cudaEventRecord(evJ, s2);

    // main: weight prep (tiny), then GEMM1
    k_prepW<<<(IN_DIM * H1 + 255) / 256, 256>>>(W1, W2, W1t, W2h);
    k_gemm_ca<128, 128, 16, 16, 4, 32, 32>
        <<<(N_NODES + 127) / 128, 512, G1_SMEM>>>(x, W1t, h1, N_NODES, IN_DIM);

    // join; gather1 (+b1+relu) -> agg1
    cudaStreamWaitEvent(0, evJ, 0);
    k_gather128<<<(N_NODES * 32 + 255) / 256, 256>>>(h1, agg1, deg, crow, dis, b1);

    // GEMM2 (W2 pre-converted fp16)
    k_gemm2_f16<<<(N_NODES + 127) / 128, 256, G2_SMEM>>>(agg1, W2h, h2, N_NODES);

    // gather2 + pool, FC
    k_gather64pool<<<(N_NODES * 32 + 255) / 256, 256>>>(h2, deg, crow, dis, b2, batch, pool);
    k_fc<<<1, 128>>>(pool, Wfc, bfc, out);
}

// round 14
// speedup vs baseline: 1.0762x; 1.0762x over previous
#include <cuda_runtime.h>
#include <cuda_fp16.h>
#include <cstdint>

// ----------------------------------------------------------------------------
// GCN: agg1 = relu(Ahat (x@W1) + b1); h2 = agg1 @ W2;
//      pool = segment_max(relu(Ahat h2 + b2), batch); out = pool @ Wfc + bfc
// R14 = R12 (best known) + ONE change: W2 pre-converted to fp16 transposed on
// the side stream (hidden under GEMM1); GEMM2 loads it via cp.async instead of
// per-block fp32->fp16 conversion (391x redundant).
// Bucketed edges (single fill pass, no count/scan); cnt zeroed by k_dis,
// pool zeroed by k_fc.
// ----------------------------------------------------------------------------

#define N_NODES 50000
#define N_EDGES 800000
#define N_GRAPHS 128
#define IN_DIM 256
#define H1 128
#define H2 64
#define OUT_DIM 10
#define CAP 192

__device__ int    g_cnt[N_NODES];        // zero at load; re-zeroed by k_dis
__device__ int    g_deg[N_NODES];
__device__ float  g_dis[N_NODES];
__device__ int    g_crow[(size_t)N_NODES * CAP];
__device__ __half g_W2h[H2 * H1];        // W2 transposed [n][k], fp16
__device__ __half g_h1[(size_t)N_NODES * H1];
__device__ __half g_agg1[(size_t)N_NODES * H1];
__device__ __half g_h2[(size_t)N_NODES * H2];
__device__ float  g_pool[N_GRAPHS * H2]; // zero at load; re-zeroed by k_fc

// ---------------------------------------------------------------- utils
__device__ __forceinline__ uint32_t f2tf(float x) {
    uint32_t u;
    asm("cvt.rna.tf32.f32 %0, %1;" : "=r"(u) : "f"(x));
    return u;
}

#define MMA_TF32(d, a, b)                                                     \
    asm volatile(                                                             \
        "mma.sync.aligned.m16n8k8.row.col.f32.tf32.tf32.f32 "                 \
        "{%0,%1,%2,%3},{%4,%5,%6,%7},{%8,%9},{%0,%1,%2,%3};"                  \
        : "+f"((d)[0]), "+f"((d)[1]), "+f"((d)[2]), "+f"((d)[3])              \
        : "r"((a)[0]), "r"((a)[1]), "r"((a)[2]), "r"((a)[3]),                 \
          "r"((b)[0]), "r"((b)[1]))

#define MMA_F16(d, a, b)                                                      \
    asm volatile(                                                             \
        "mma.sync.aligned.m16n8k16.row.col.f32.f16.f16.f32 "                  \
        "{%0,%1,%2,%3},{%4,%5,%6,%7},{%8,%9},{%0,%1,%2,%3};"                  \
        : "+f"((d)[0]), "+f"((d)[1]), "+f"((d)[2]), "+f"((d)[3])              \
        : "r"((a)[0]), "r"((a)[1]), "r"((a)[2]), "r"((a)[3]),                 \
          "r"((b)[0]), "r"((b)[1]))

__device__ __forceinline__ void cp16(uint32_t saddr, const void* gaddr, int sz) {
    asm volatile("cp.async.cg.shared.global [%0], [%1], 16, %2;"
                 :: "r"(saddr), "l"(gaddr), "r"(sz));
}

__device__ __forceinline__ float4 ldh4(const __half* p) {
    uint2 u = *(const uint2*)p;
    float2 a = __half22float2(*(__half2*)&u.x);
    float2 b = __half22float2(*(__half2*)&u.y);
    return make_float4(a.x, a.y, b.x, b.y);
}

// ---------------------------------------------------------------- W2 prep (once, hidden on side stream)
__global__ void k_prepW2(const float* __restrict__ W2, __half* __restrict__ W2h)
{
    int i = blockIdx.x * blockDim.x + threadIdx.x;
    if (i < H1 * H2) {
        int k = i >> 6, n = i & 63;
        W2h[n * H1 + k] = __float2half(W2[i]);
    }
}

// ---------------------------------------------------------------- bucket fill
__global__ void k_fill(const int* __restrict__ row, const int* __restrict__ col,
                       int* __restrict__ cnt, int* __restrict__ crow)
{
    int i = blockIdx.x * blockDim.x + threadIdx.x;
    if (i * 4 >= N_EDGES) return;
    int4 r = *(const int4*)(row + i * 4);
    int4 c = *(const int4*)(col + i * 4);
    int p0 = atomicAdd(&cnt[c.x], 1);
    int p1 = atomicAdd(&cnt[c.y], 1);
    int p2 = atomicAdd(&cnt[c.z], 1);
    int p3 = atomicAdd(&cnt[c.w], 1);
    crow[(size_t)c.x * CAP + p0] = r.x;
    crow[(size_t)c.y * CAP + p1] = r.y;
    crow[(size_t)c.z * CAP + p2] = r.z;
    crow[(size_t)c.w * CAP + p3] = r.w;
}

__global__ void k_dis(int* __restrict__ cnt, int* __restrict__ deg,
                      float* __restrict__ dis)
{
    int i = blockIdx.x * blockDim.x + threadIdx.x;
    if (i < N_NODES) {
        int v = cnt[i];
        deg[i] = v;
        dis[i] = rsqrtf((float)(v + 1));
        cnt[i] = 0;
    }
}

// ---------------------------------------------------------------- GEMM1 (tf32, 3-stage cp.async, fp16 out)
template<int BM, int BN, int BK, int WARPS, int WARPS_M, int WM, int WN>
__global__ void __launch_bounds__(WARPS * 32)
k_gemm_ca(const float* __restrict__ A, const float* __restrict__ B,
          __half* __restrict__ C, int M, int K)
{
    constexpr int MT = WM / 16, NT = WN / 8;
    constexpr int SA = BK + 4;
    constexpr int SB = BN + 8;
    extern __shared__ float dyn[];
    float* As = dyn;
    float* Bs = dyn + 3 * BM * SA;

    const int tid = threadIdx.x, wid = tid >> 5, lane = tid & 31;
    const int wm = wid % WARPS_M, wn = wid / WARPS_M;
    const int g = lane >> 2, tig = lane & 3;
    const int m0 = blockIdx.x * BM;

    float acc[MT][NT][4];
#pragma unroll
    for (int i = 0; i < MT; i++)
#pragma unroll
        for (int j = 0; j < NT; j++)
#pragma unroll
            for (int q = 0; q < 4; q++) acc[i][j][q] = 0.f;

    auto loadTiles = [&](int buf, int k0) {
        float* Ab = As + buf * BM * SA;
        float* Bb = Bs + buf * BK * SB;
#pragma unroll
        for (int i = tid; i < BM * BK / 4; i += WARPS * 32) {
            int r = i / (BK / 4), c4 = i % (BK / 4);
            cp16((uint32_t)__cvta_generic_to_shared(&Ab[r * SA + c4 * 4]),
                 A + (size_t)(m0 + r) * K + k0 + c4 * 4,
                 (m0 + r < M) ? 16 : 0);
        }
#pragma unroll
        for (int i = tid; i < BK * BN / 4; i += WARPS * 32) {
            int kk = i / (BN / 4), c4 = i % (BN / 4);
            cp16((uint32_t)__cvta_generic_to_shared(&Bb[kk * SB + c4 * 4]),
                 B + (size_t)(k0 + kk) * BN + c4 * 4, 16);
        }
        asm volatile("cp.async.commit_group;");
    };

    const int nk = K / BK;
    loadTiles(0, 0);
    loadTiles(1, BK);
    for (int t = 0; t < nk; t++) {
        if (t + 2 < nk) {
            loadTiles((t + 2) % 3, (t + 2) * BK);
            asm volatile("cp.async.wait_group 2;");
        } else if (t + 1 < nk) {
            asm volatile("cp.async.wait_group 1;");
        } else {
            asm volatile("cp.async.wait_group 0;");
        }
        __syncthreads();
        const int buf = t % 3;
        const float* Ab = As + buf * BM * SA;
        const float* Bb = Bs + buf * BK * SB;

#pragma unroll
        for (int kk = 0; kk < BK / 8; kk++) {
            uint32_t af[MT][4], bf[NT][2];
#pragma unroll
            for (int mt = 0; mt < MT; mt++) {
                int r = wm * WM + mt * 16;
                af[mt][0] = f2tf(Ab[(r + g)     * SA + kk * 8 + tig]);
                af[mt][1] = f2tf(Ab[(r + g + 8) * SA + kk * 8 + tig]);
                af[mt][2] = f2tf(Ab[(r + g)     * SA + kk * 8 + tig + 4]);
                af[mt][3] = f2tf(Ab[(r + g + 8) * SA + kk * 8 + tig + 4]);
            }
#pragma unroll
            for (int nt = 0; nt < NT; nt++) {
                int c = wn * WN + nt * 8;
                bf[nt][0] = f2tf(Bb[(kk * 8 + tig)     * SB + c + g]);
                bf[nt][1] = f2tf(Bb[(kk * 8 + tig + 4) * SB + c + g]);
            }
#pragma unroll
            for (int mt = 0; mt < MT; mt++)
#pragma unroll
                for (int nt = 0; nt < NT; nt++)
                    MMA_TF32(acc[mt][nt], af[mt], bf[nt]);
        }
        __syncthreads();
    }

#pragma unroll
    for (int mt = 0; mt < MT; mt++) {
        int r0 = m0 + wm * WM + mt * 16 + g;
#pragma unroll
        for (int nt = 0; nt < NT; nt++) {
            int c = wn * WN + nt * 8 + 2 * tig;
            if (r0 < M)
                *(__half2*)(C + (size_t)r0 * BN + c) =
                    __floats2half2_rn(acc[mt][nt][0], acc[mt][nt][1]);
            if (r0 + 8 < M)
                *(__half2*)(C + (size_t)(r0 + 8) * BN + c) =
                    __floats2half2_rn(acc[mt][nt][2], acc[mt][nt][3]);
        }
    }
}

#define G1_SMEM (3 * (128 * 20 + 16 * 136) * 4)

// ---------------------------------------------------------------- GEMM2 (fp16 mma; W2h via cp.async)
#define G2_SA 136
#define G2_SB 136
#define G2_SMEM ((128 * G2_SA + 64 * G2_SB) * 2)

__global__ void __launch_bounds__(256)
k_gemm2_f16(const __half* __restrict__ A, const __half* __restrict__ W2h,
            __half* __restrict__ C, int M)
{
    extern __shared__ __half sm[];
    __half* As  = sm;                     // [128][G2_SA]
    __half* Bs2 = sm + 128 * G2_SA;       // [64][G2_SB]  (n-major, k contiguous)

    const int tid = threadIdx.x, wid = tid >> 5, lane = tid & 31;
    const int wm = wid % 4, wn = wid / 4;
    const int g = lane >> 2, tig = lane & 3;
    const int m0 = blockIdx.x * 128;

#pragma unroll
    for (int i = tid; i < 128 * 16; i += 256) {
        int r = i / 16, c8 = i % 16;
        cp16((uint32_t)__cvta_generic_to_shared(&As[r * G2_SA + c8 * 8]),
             A + (size_t)(m0 + r) * 128 + c8 * 8,
             (m0 + r < M) ? 16 : 0);
    }
#pragma unroll
    for (int i = tid; i < 64 * 16; i += 256) {
        int n = i / 16, c8 = i % 16;
        cp16((uint32_t)__cvta_generic_to_shared(&Bs2[n * G2_SB + c8 * 8]),
             W2h + n * H1 + c8 * 8, 16);
    }
    asm volatile("cp.async.commit_group;");
    asm volatile("cp.async.wait_group 0;");
    __syncthreads();

    float acc[2][4][4];
#pragma unroll
    for (int i = 0; i < 2; i++)
#pragma unroll
        for (int j = 0; j < 4; j++)
#pragma unroll
            for (int q = 0; q < 4; q++) acc[i][j][q] = 0.f;

#pragma unroll
    for (int kk = 0; kk < 8; kk++) {
        uint32_t af[2][4], bf[4][2];
#pragma unroll
        for (int mt = 0; mt < 2; mt++) {
            int r = wm * 32 + mt * 16;
            af[mt][0] = *(const uint32_t*)&As[(r + g)     * G2_SA + kk * 16 + 2 * tig];
            af[mt][1] = *(const uint32_t*)&As[(r + g + 8) * G2_SA + kk * 16 + 2 * tig];
            af[mt][2] = *(const uint32_t*)&As[(r + g)     * G2_SA + kk * 16 + 8 + 2 * tig];
            af[mt][3] = *(const uint32_t*)&As[(r + g + 8) * G2_SA + kk * 16 + 8 + 2 * tig];
        }
#pragma unroll
        for (int nt = 0; nt < 4; nt++) {
            int c = wn * 32 + nt * 8;
            bf[nt][0] = *(const uint32_t*)&Bs2[(c + g) * G2_SB + kk * 16 + 2 * tig];
            bf[nt][1] = *(const uint32_t*)&Bs2[(c + g) * G2_SB + kk * 16 + 8 + 2 * tig];
        }
#pragma unroll
        for (int mt = 0; mt < 2; mt++)
#pragma unroll
            for (int nt = 0; nt < 4; nt++)
                MMA_F16(acc[mt][nt], af[mt], bf[nt]);
    }

#pragma unroll
    for (int mt = 0; mt < 2; mt++) {
        int r0 = m0 + wm * 32 + mt * 16 + g;
#pragma unroll
        for (int nt = 0; nt < 4; nt++) {
            int c = wn * 32 + nt * 8 + 2 * tig;
            if (r0 < M)
                *(__half2*)(C + (size_t)r0 * 64 + c) =
                    __floats2half2_rn(acc[mt][nt][0], acc[mt][nt][1]);
            if (r0 + 8 < M)
                *(__half2*)(C + (size_t)(r0 + 8) * 64 + c) =
                    __floats2half2_rn(acc[mt][nt][2], acc[mt][nt][3]);
        }
    }
}

// ---------------------------------------------------------------- gather1 (+bias+relu); norm on the fly (R12 form)
__global__ void k_gather128(const __half* __restrict__ h, __half* __restrict__ agg,
                            const int* __restrict__ deg, const int* __restrict__ crow,
                            const float* __restrict__ dis, const float* __restrict__ bias)
{
    int node = (blockIdx.x * blockDim.x + threadIdx.x) >> 5;
    int lane = threadIdx.x & 31;
    if (node >= N_NODES) return;

    float dnode = dis[node];
    float dd = dnode * dnode;
    float4 acc = ldh4(h + (size_t)node * 128 + lane * 4);
    acc.x *= dd; acc.y *= dd; acc.z *= dd; acc.w *= dd;

    const int* base = crow + (size_t)node * CAP;
    int e = deg[node];
    int j = 0;
    for (; j + 7 < e; j += 8) {
        int p[8];
#pragma unroll
        for (int q = 0; q < 8; q++) p[q] = __ldg(base + j + q);
        float4 v[8];
        float nn[8];
#pragma unroll
        for (int q = 0; q < 8; q++) {
            v[q] = ldh4(h + (size_t)p[q] * 128 + lane * 4);
            nn[q] = __ldg(&dis[p[q]]) * dnode;
        }
#pragma unroll
        for (int q = 0; q < 8; q++) {
            acc.x = fmaf(v[q].x, nn[q], acc.x); acc.y = fmaf(v[q].y, nn[q], acc.y);
            acc.z = fmaf(v[q].z, nn[q], acc.z); acc.w = fmaf(v[q].w, nn[q], acc.w);
        }
    }
    for (; j + 3 < e; j += 4) {
        int p[4];
#pragma unroll
        for (int q = 0; q < 4; q++) p[q] = __ldg(base + j + q);
#pragma unroll
        for (int q = 0; q < 4; q++) {
            float4 v = ldh4(h + (size_t)p[q] * 128 + lane * 4);
            float n = __ldg(&dis[p[q]]) * dnode;
            acc.x = fmaf(v.x, n, acc.x); acc.y = fmaf(v.y, n, acc.y);
            acc.z = fmaf(v.z, n, acc.z); acc.w = fmaf(v.w, n, acc.w);
        }
    }
    for (; j < e; j++) {
        int p = __ldg(base + j);
        float n = __ldg(&dis[p]) * dnode;
        float4 v = ldh4(h + (size_t)p * 128 + lane * 4);
        acc.x = fmaf(v.x, n, acc.x); acc.y = fmaf(v.y, n, acc.y);
        acc.z = fmaf(v.z, n, acc.z); acc.w = fmaf(v.w, n, acc.w);
    }
    float4 bb = *(const float4*)(bias + lane * 4);
    acc.x = fmaxf(acc.x + bb.x, 0.f); acc.y = fmaxf(acc.y + bb.y, 0.f);
    acc.z = fmaxf(acc.z + bb.z, 0.f); acc.w = fmaxf(acc.w + bb.w, 0.f);
    uint2 st;
    *(__half2*)&st.x = __floats2half2_rn(acc.x, acc.y);
    *(__half2*)&st.y = __floats2half2_rn(acc.z, acc.w);
    *(uint2*)(agg + (size_t)node * 128 + lane * 4) = st;
}

// ---------------------------------------------------------------- gather2 + max-pool; norm on the fly (R12 form)
__global__ void k_gather64pool(const __half* __restrict__ h2,
                               const int* __restrict__ deg, const int* __restrict__ crow,
                               const float* __restrict__ dis, const float* __restrict__ b2,
                               const int* __restrict__ batch, float* __restrict__ pool)
{
    int node = (blockIdx.x * blockDim.x + threadIdx.x) >> 5;
    int lane = threadIdx.x & 31;
    if (node >= N_NODES) return;

    float dnode = dis[node];
    float dd = dnode * dnode;
    float2 acc = __half22float2(*(const __half2*)(h2 + (size_t)node * 64 + lane * 2));
    acc.x *= dd; acc.y *= dd;

    const int* base = crow + (size_t)node * CAP;
    int e = deg[node];
    int j = 0;
    for (; j + 7 < e; j += 8) {
        int p[8];
#pragma unroll
        for (int q = 0; q < 8; q++) p[q] = __ldg(base + j + q);
        float2 v[8];
        float nn[8];
#pragma unroll
        for (int q = 0; q < 8; q++) {
            v[q] = __half22float2(*(const __half2*)(h2 + (size_t)p[q] * 64 + lane * 2));
            nn[q] = __ldg(&dis[p[q]]) * dnode;
        }
#pragma unroll
        for (int q = 0; q < 8; q++) {
            acc.x = fmaf(v[q].x, nn[q], acc.x); acc.y = fmaf(v[q].y, nn[q], acc.y);
        }
    }
    for (; j + 3 < e; j += 4) {
        int p[4];
#pragma unroll
        for (int q = 0; q < 4; q++) p[q] = __ldg(base + j + q);
#pragma unroll
        for (int q = 0; q < 4; q++) {
            float2 v = __half22float2(*(const __half2*)(h2 + (size_t)p[q] * 64 + lane * 2));
            float n = __ldg(&dis[p[q]]) * dnode;
            acc.x = fmaf(v.x, n, acc.x); acc.y = fmaf(v.y, n, acc.y);
        }
    }
    for (; j < e; j++) {
        int p = __ldg(base + j);
        float n = __ldg(&dis[p]) * dnode;
        float2 v = __half22float2(*(const __half2*)(h2 + (size_t)p * 64 + lane * 2));
        acc.x = fmaf(v.x, n, acc.x); acc.y = fmaf(v.y, n, acc.y);
    }
    float2 bb = *(const float2*)(b2 + lane * 2);
    acc.x = fmaxf(acc.x + bb.x, 0.f);
    acc.y = fmaxf(acc.y + bb.y, 0.f);

    int gph = batch[node];
    atomicMax((unsigned int*)&pool[gph * H2 + lane * 2],     __float_as_uint(acc.x));
    atomicMax((unsigned int*)&pool[gph * H2 + lane * 2 + 1], __float_as_uint(acc.y));
}

// ---------------------------------------------------------------- final FC (re-zeroes pool after use)
__global__ void k_fc(float* __restrict__ pool, const float* __restrict__ Wfc,
                     const float* __restrict__ bfc, float* __restrict__ out)
{
    __shared__ float w[H2 * OUT_DIM];
    __shared__ float bb[OUT_DIM];
    int tid = threadIdx.x;
    for (int i = tid; i < H2 * OUT_DIM; i += blockDim.x) w[i] = Wfc[i];
    if (tid < OUT_DIM) bb[tid] = bfc[tid];
    __syncthreads();
    if (tid < N_GRAPHS) {
        float acc[OUT_DIM];
#pragma unroll
        for (int j = 0; j < OUT_DIM; j++) acc[j] = bb[j];
        for (int k = 0; k < H2; k++) {
            float g = pool[tid * H2 + k];
#pragma unroll
            for (int j = 0; j < OUT_DIM; j++) acc[j] = fmaf(g, w[k * OUT_DIM + j], acc[j]);
        }
#pragma unroll
        for (int j = 0; j < OUT_DIM; j++) out[tid * OUT_DIM + j] = acc[j];
    }
    __syncthreads();
    for (int i = tid; i < N_GRAPHS * H2; i += blockDim.x) pool[i] = 0.f;
}

// ---------------------------------------------------------------- launch
extern "C" void kernel_launch(void* const* d_in, const int* in_sizes, int n_in,
                              void* d_out, int out_size)
{
    const float* x    = (const float*)d_in[0];
    const int*   ei   = (const int*)d_in[1];
    const int*   batch= (const int*)d_in[2];
    const float* W1   = (const float*)d_in[3];
    const float* b1   = (const float*)d_in[4];
    const float* W2   = (const float*)d_in[5];
    const float* b2   = (const float*)d_in[6];
    const float* Wfc  = (const float*)d_in[7];
    const float* bfc  = (const float*)d_in[8];
    float* out = (float*)d_out;

    const int* row = ei;
    const int* col = ei + N_EDGES;

    int *cnt, *deg, *crow;
    float *dis, *pool;
    __half *h1, *agg1, *h2, *W2h;
    cudaGetSymbolAddress((void**)&cnt,  g_cnt);
    cudaGetSymbolAddress((void**)&deg,  g_deg);
    cudaGetSymbolAddress((void**)&dis,  g_dis);
    cudaGetSymbolAddress((void**)&crow, g_crow);
    cudaGetSymbolAddress((void**)&W2h,  g_W2h);
    cudaGetSymbolAddress((void**)&h1,   g_h1);
    cudaGetSymbolAddress((void**)&agg1, g_agg1);
    cudaGetSymbolAddress((void**)&h2,   g_h2);
    cudaGetSymbolAddress((void**)&pool, g_pool);

    cudaFuncSetAttribute((const void*)k_gemm_ca<128, 128, 16, 16, 4, 32, 32>,
                         cudaFuncAttributeMaxDynamicSharedMemorySize, G1_SMEM);
    cudaFuncSetAttribute(k_gemm2_f16,
                         cudaFuncAttributeMaxDynamicSharedMemorySize, G2_SMEM);

    cudaStream_t s2;
    cudaStreamCreateWithFlags(&s2, cudaStreamNonBlocking);
    cudaEvent_t evF, evJ;
    cudaEventCreateWithFlags(&evF, cudaEventDisableTiming);
    cudaEventCreateWithFlags(&evJ, cudaEventDisableTiming);

    // fork: W2 prep + bucket fill + dis on s2 (all hidden under GEMM1)
    cudaEventRecord(evF, 0);
    cudaStreamWaitEvent(s2, evF, 0);
    k_prepW2<<<(H1 * H2 + 255) / 256, 256, 0, s2>>>(W2, W2h);
    k_fill<<<(N_EDGES / 4 + 255) / 256, 256, 0, s2>>>(row, col, cnt, crow);
    k_dis<<<(N_NODES + 255) / 256, 256, 0, s2>>>(cnt, deg, dis);
    cudaEventRecord(evJ, s2);

    // main: GEMM1
    k_gemm_ca<128, 128, 16, 16, 4, 32, 32>
        <<<(N_NODES + 127) / 128, 512, G1_SMEM>>>(x, W1, h1, N_NODES, IN_DIM);

    // join; gather1 (+b1+relu) -> agg1
    cudaStreamWaitEvent(0, evJ, 0);
    k_gather128<<<(N_NODES * 32 + 255) / 256, 256>>>(h1, agg1, deg, crow, dis, b1);

    // GEMM2 (W2 pre-converted fp16)
    k_gemm2_f16<<<(N_NODES + 127) / 128, 256, G2_SMEM>>>(agg1, W2h, h2, N_NODES);

    // gather2 + pool, FC
    k_gather64pool<<<(N_NODES * 32 + 255) / 256, 256>>>(h2, deg, crow, dis, b2, batch, pool);
    k_fc<<<1, 128>>>(pool, Wfc, bfc, out);
}

// round 15
// speedup vs baseline: 1.1466x; 1.0655x over previous
#include <cuda_runtime.h>
#include <cuda_fp16.h>
#include <cstdint>

// ----------------------------------------------------------------------------
// GCN: agg1 = relu(Ahat (x@W1) + b1); h2 = agg1 @ W2;
//      pool = segment_max(relu(Ahat h2 + b2), batch); out = pool @ Wfc + bfc
// R15 = R14 + GEMM1 switched to fp16 mma (m16n8k16): W1 pre-converted to fp16
// [n][k] on side stream; A tile converted fp32->fp16 once during smem staging
// (register-pipelined LDG->STS); zero cvt in the MMA inner loop.
// Bucketed edges (single fill pass); cnt zeroed by k_dis, pool by k_fc.
// ----------------------------------------------------------------------------

#define N_NODES 50000
#define N_EDGES 800000
#define N_GRAPHS 128
#define IN_DIM 256
#define H1 128
#define H2 64
#define OUT_DIM 10
#define CAP 192

__device__ int    g_cnt[N_NODES];        // zero at load; re-zeroed by k_dis
__device__ int    g_deg[N_NODES];
__device__ float  g_dis[N_NODES];
__device__ int    g_crow[(size_t)N_NODES * CAP];
__device__ __half g_W1h[H1 * IN_DIM];    // W1 transposed [n][k], fp16
__device__ __half g_W2h[H2 * H1];        // W2 transposed [n][k], fp16
__device__ __half g_h1[(size_t)N_NODES * H1];
__device__ __half g_agg1[(size_t)N_NODES * H1];
__device__ __half g_h2[(size_t)N_NODES * H2];
__device__ float  g_pool[N_GRAPHS * H2]; // zero at load; re-zeroed by k_fc

// ---------------------------------------------------------------- utils
#define MMA_F16(d, a, b)                                                      \
    asm volatile(                                                             \
        "mma.sync.aligned.m16n8k16.row.col.f32.f16.f16.f32 "                  \
        "{%0,%1,%2,%3},{%4,%5,%6,%7},{%8,%9},{%0,%1,%2,%3};"                  \
        : "+f"((d)[0]), "+f"((d)[1]), "+f"((d)[2]), "+f"((d)[3])              \
        : "r"((a)[0]), "r"((a)[1]), "r"((a)[2]), "r"((a)[3]),                 \
          "r"((b)[0]), "r"((b)[1]))

__device__ __forceinline__ void cp16(uint32_t saddr, const void* gaddr, int sz) {
    asm volatile("cp.async.cg.shared.global [%0], [%1], 16, %2;"
                 :: "r"(saddr), "l"(gaddr), "r"(sz));
}

__device__ __forceinline__ float4 ldh4(const __half* p) {
    uint2 u = *(const uint2*)p;
    float2 a = __half22float2(*(__half2*)&u.x);
    float2 b = __half22float2(*(__half2*)&u.y);
    return make_float4(a.x, a.y, b.x, b.y);
}

// ---------------------------------------------------------------- weight prep (side stream, before GEMM1)
__global__ void k_prepW(const float* __restrict__ W1, const float* __restrict__ W2,
                        __half* __restrict__ W1h, __half* __restrict__ W2h)
{
    int i = blockIdx.x * blockDim.x + threadIdx.x;
    if (i < IN_DIM * H1) {              // W1[k][n] -> W1h[n][k]
        int k = i >> 7, n = i & 127;
        W1h[n * IN_DIM + k] = __float2half(W1[i]);
    }
    if (i < H1 * H2) {                  // W2[k][n] -> W2h[n][k]
        int k = i >> 6, n = i & 63;
        W2h[n * H1 + k] = __float2half(W2[i]);
    }
}

// ---------------------------------------------------------------- bucket fill
__global__ void k_fill(const int* __restrict__ row, const int* __restrict__ col,
                       int* __restrict__ cnt, int* __restrict__ crow)
{
    int i = blockIdx.x * blockDim.x + threadIdx.x;
    if (i * 4 >= N_EDGES) return;
    int4 r = *(const int4*)(row + i * 4);
    int4 c = *(const int4*)(col + i * 4);
    int p0 = atomicAdd(&cnt[c.x], 1);
    int p1 = atomicAdd(&cnt[c.y], 1);
    int p2 = atomicAdd(&cnt[c.z], 1);
    int p3 = atomicAdd(&cnt[c.w], 1);
    crow[(size_t)c.x * CAP + p0] = r.x;
    crow[(size_t)c.y * CAP + p1] = r.y;
    crow[(size_t)c.z * CAP + p2] = r.z;
    crow[(size_t)c.w * CAP + p3] = r.w;
}

__global__ void k_dis(int* __restrict__ cnt, int* __restrict__ deg,
                      float* __restrict__ dis)
{
    int i = blockIdx.x * blockDim.x + threadIdx.x;
    if (i < N_NODES) {
        int v = cnt[i];
        deg[i] = v;
        dis[i] = rsqrtf((float)(v + 1));
        cnt[i] = 0;
    }
}

// ---------------------------------------------------------------- GEMM1 (fp16 mma, A staged fp32->fp16, B=W1h cp.async)
// 512 thr, 16 warps (4x4), warp tile 32x32. K=256 in 8 tiles of BK=32.
#define G1_SA 40    // half stride per A row (32 + 8) -> conflict-free frags
#define G1_SB 40

__global__ void __launch_bounds__(512)
k_gemm1_f16(const float* __restrict__ A, const __half* __restrict__ W1h,
            __half* __restrict__ C, int M)
{
    __shared__ __half As[2][128 * G1_SA];
    __shared__ __half Bs[2][128 * G1_SB];

    const int tid = threadIdx.x, wid = tid >> 5, lane = tid & 31;
    const int wm = wid % 4, wn = wid / 4;
    const int g = lane >> 2, tig = lane & 3;
    const int m0 = blockIdx.x * 128;

    // staging indices: 4 threads per row, 2 float4 each (32 fp32 per row)
    const int ar = tid >> 2;            // row 0..127
    const int af4 = (tid & 3) * 2;      // float4 index 0,2,4,6
    const bool arow_ok = (m0 + ar < M);

    float4 ra0, ra1;
    auto ldA = [&](int t) {
        if (arow_ok) {
            const float* src = A + (size_t)(m0 + ar) * IN_DIM + t * 32 + af4 * 4;
            ra0 = *(const float4*)src;
            ra1 = *(const float4*)(src + 4);
        } else {
            ra0 = make_float4(0.f, 0.f, 0.f, 0.f);
            ra1 = ra0;
        }
    };
    auto stA = [&](int buf) {
        __half2* dst = (__half2*)&As[buf][ar * G1_SA + af4 * 4];
        dst[0] = __floats2half2_rn(ra0.x, ra0.y);
        dst[1] = __floats2half2_rn(ra0.z, ra0.w);
        dst[2] = __floats2half2_rn(ra1.x, ra1.y);
        dst[3] = __floats2half2_rn(ra1.z, ra1.w);
    };
    // B tile: 128 rows (n) x 32 halfs (k) = 512 x 16B chunks, 1 per thread
    const int bn = tid >> 2;
    const int bc = tid & 3;
    auto ldB = [&](int buf, int t) {
        cp16((uint32_t)__cvta_generic_to_shared(&Bs[buf][bn * G1_SB + bc * 8]),
             W1h + bn * IN_DIM + t * 32 + bc * 8, 16);
        asm volatile("cp.async.commit_group;");
    };

    float acc[2][4][4];
#pragma unroll
    for (int i = 0; i < 2; i++)
#pragma unroll
        for (int j = 0; j < 4; j++)
#pragma unroll
            for (int q = 0; q < 4; q++) acc[i][j][q] = 0.f;

    // prologue: tile 0 into buf 0; prefetch A tile 1 into regs
    ldA(0);
    stA(0);
    ldB(0, 0);
    ldA(1);
    asm volatile("cp.async.wait_group 0;");
    __syncthreads();

#pragma unroll
    for (int t = 0; t < 8; t++) {
        const int cur = t & 1, nxt = cur ^ 1;
        if (t < 7) {
            ldB(nxt, t + 1);
            stA(nxt);                    // A tile t+1 from regs
            if (t < 6) ldA(t + 2);       // prefetch next A
        }
#pragma unroll
        for (int kk = 0; kk < 2; kk++) {
            uint32_t af[2][4], bf[4][2];
#pragma unroll
            for (int mt = 0; mt < 2; mt++) {
                int r = wm * 32 + mt * 16;
                af[mt][0] = *(const uint32_t*)&As[cur][(r + g)     * G1_SA + kk * 16 + 2 * tig];
                af[mt][1] = *(const uint32_t*)&As[cur][(r + g + 8) * G1_SA + kk * 16 + 2 * tig];
                af[mt][2] = *(const uint32_t*)&As[cur][(r + g)     * G1_SA + kk * 16 + 8 + 2 * tig];
                af[mt][3] = *(const uint32_t*)&As[cur][(r + g + 8) * G1_SA + kk * 16 + 8 + 2 * tig];
            }
#pragma unroll
            for (int nt = 0; nt < 4; nt++) {
                int c = wn * 32 + nt * 8;
                bf[nt][0] = *(const uint32_t*)&Bs[cur][(c + g) * G1_SB + kk * 16 + 2 * tig];
                bf[nt][1] = *(const uint32_t*)&Bs[cur][(c + g) * G1_SB + kk * 16 + 8 + 2 * tig];
            }
#pragma unroll
            for (int mt = 0; mt < 2; mt++)
#pragma unroll
                for (int nt = 0; nt < 4; nt++)
                    MMA_F16(acc[mt][nt], af[mt], bf[nt]);
        }
        if (t < 7)
            asm volatile("cp.async.wait_group 0;");
        __syncthreads();
    }

#pragma unroll
    for (int mt = 0; mt < 2; mt++) {
        int r0 = m0 + wm * 32 + mt * 16 + g;
#pragma unroll
        for (int nt = 0; nt < 4; nt++) {
            int c = wn * 32 + nt * 8 + 2 * tig;
            if (r0 < M)
                *(__half2*)(C + (size_t)r0 * H1 + c) =
                    __floats2half2_rn(acc[mt][nt][0], acc[mt][nt][1]);
            if (r0 + 8 < M)
                *(__half2*)(C + (size_t)(r0 + 8) * H1 + c) =
                    __floats2half2_rn(acc[mt][nt][2], acc[mt][nt][3]);
        }
    }
}

// ---------------------------------------------------------------- GEMM2 (fp16 mma; W2h via cp.async)
#define G2_SA 136
#define G2_SB 136
#define G2_SMEM ((128 * G2_SA + 64 * G2_SB) * 2)

__global__ void __launch_bounds__(256)
k_gemm2_f16(const __half* __restrict__ A, const __half* __restrict__ W2h,
            __half* __restrict__ C, int M)
{
    extern __shared__ __half sm[];
    __half* As  = sm;
    __half* Bs2 = sm + 128 * G2_SA;

    const int tid = threadIdx.x, wid = tid >> 5, lane = tid & 31;
    const int wm = wid % 4, wn = wid / 4;
    const int g = lane >> 2, tig = lane & 3;
    const int m0 = blockIdx.x * 128;

#pragma unroll
    for (int i = tid; i < 128 * 16; i += 256) {
        int r = i / 16, c8 = i % 16;
        cp16((uint32_t)__cvta_generic_to_shared(&As[r * G2_SA + c8 * 8]),
             A + (size_t)(m0 + r) * 128 + c8 * 8,
             (m0 + r < M) ? 16 : 0);
    }
#pragma unroll
    for (int i = tid; i < 64 * 16; i += 256) {
        int n = i / 16, c8 = i % 16;
        cp16((uint32_t)__cvta_generic_to_shared(&Bs2[n * G2_SB + c8 * 8]),
             W2h + n * H1 + c8 * 8, 16);
    }
    asm volatile("cp.async.commit_group;");
    asm volatile("cp.async.wait_group 0;");
    __syncthreads();

    float acc[2][4][4];
#pragma unroll
    for (int i = 0; i < 2; i++)
#pragma unroll
        for (int j = 0; j < 4; j++)
#pragma unroll
            for (int q = 0; q < 4; q++) acc[i][j][q] = 0.f;

#pragma unroll
    for (int kk = 0; kk < 8; kk++) {
        uint32_t af[2][4], bf[4][2];
#pragma unroll
        for (int mt = 0; mt < 2; mt++) {
            int r = wm * 32 + mt * 16;
            af[mt][0] = *(const uint32_t*)&As[(r + g)     * G2_SA + kk * 16 + 2 * tig];
            af[mt][1] = *(const uint32_t*)&As[(r + g + 8) * G2_SA + kk * 16 + 2 * tig];
            af[mt][2] = *(const uint32_t*)&As[(r + g)     * G2_SA + kk * 16 + 8 + 2 * tig];
            af[mt][3] = *(const uint32_t*)&As[(r + g + 8) * G2_SA + kk * 16 + 8 + 2 * tig];
        }
#pragma unroll
        for (int nt = 0; nt < 4; nt++) {
            int c = wn * 32 + nt * 8;
            bf[nt][0] = *(const uint32_t*)&Bs2[(c + g) * G2_SB + kk * 16 + 2 * tig];
            bf[nt][1] = *(const uint32_t*)&Bs2[(c + g) * G2_SB + kk * 16 + 8 + 2 * tig];
        }
#pragma unroll
        for (int mt = 0; mt < 2; mt++)
#pragma unroll
            for (int nt = 0; nt < 4; nt++)
                MMA_F16(acc[mt][nt], af[mt], bf[nt]);
    }

#pragma unroll
    for (int mt = 0; mt < 2; mt++) {
        int r0 = m0 + wm * 32 + mt * 16 + g;
#pragma unroll
        for (int nt = 0; nt < 4; nt++) {
            int c = wn * 32 + nt * 8 + 2 * tig;
            if (r0 < M)
                *(__half2*)(C + (size_t)r0 * 64 + c) =
                    __floats2half2_rn(acc[mt][nt][0], acc[mt][nt][1]);
            if (r0 + 8 < M)
                *(__half2*)(C + (size_t)(r0 + 8) * 64 + c) =
                    __floats2half2_rn(acc[mt][nt][2], acc[mt][nt][3]);
        }
    }
}

// ---------------------------------------------------------------- gather1 (+bias+relu); norm on the fly
__global__ void k_gather128(const __half* __restrict__ h, __half* __restrict__ agg,
                            const int* __restrict__ deg, const int* __restrict__ crow,
                            const float* __restrict__ dis, const float* __restrict__ bias)
{
    int node = (blockIdx.x * blockDim.x + threadIdx.x) >> 5;
    int lane = threadIdx.x & 31;
    if (node >= N_NODES) return;

    float dnode = dis[node];
    float dd = dnode * dnode;
    float4 acc = ldh4(h + (size_t)node * 128 + lane * 4);
    acc.x *= dd; acc.y *= dd; acc.z *= dd; acc.w *= dd;

    const int* base = crow + (size_t)node * CAP;
    int e = deg[node];
    int j = 0;
    for (; j + 7 < e; j += 8) {
        int p[8];
#pragma unroll
        for (int q = 0; q < 8; q++) p[q] = __ldg(base + j + q);
        float4 v[8];
        float nn[8];
#pragma unroll
        for (int q = 0; q < 8; q++) {
            v[q] = ldh4(h + (size_t)p[q] * 128 + lane * 4);
            nn[q] = __ldg(&dis[p[q]]) * dnode;
        }
#pragma unroll
        for (int q = 0; q < 8; q++) {
            acc.x = fmaf(v[q].x, nn[q], acc.x); acc.y = fmaf(v[q].y, nn[q], acc.y);
            acc.z = fmaf(v[q].z, nn[q], acc.z); acc.w = fmaf(v[q].w, nn[q], acc.w);
        }
    }
    for (; j + 3 < e; j += 4) {
        int p[4];
#pragma unroll
        for (int q = 0; q < 4; q++) p[q] = __ldg(base + j + q);
#pragma unroll
        for (int q = 0; q < 4; q++) {
            float4 v = ldh4(h + (size_t)p[q] * 128 + lane * 4);
            float n = __ldg(&dis[p[q]]) * dnode;
            acc.x = fmaf(v.x, n, acc.x); acc.y = fmaf(v.y, n, acc.y);
            acc.z = fmaf(v.z, n, acc.z); acc.w = fmaf(v.w, n, acc.w);
        }
    }
    for (; j < e; j++) {
        int p = __ldg(base + j);
        float n = __ldg(&dis[p]) * dnode;
        float4 v = ldh4(h + (size_t)p * 128 + lane * 4);
        acc.x = fmaf(v.x, n, acc.x); acc.y = fmaf(v.y, n, acc.y);
        acc.z = fmaf(v.z, n, acc.z); acc.w = fmaf(v.w, n, acc.w);
    }
    float4 bb = *(const float4*)(bias + lane * 4);
    acc.x = fmaxf(acc.x + bb.x, 0.f); acc.y = fmaxf(acc.y + bb.y, 0.f);
    acc.z = fmaxf(acc.z + bb.z, 0.f); acc.w = fmaxf(acc.w + bb.w, 0.f);
    uint2 st;
    *(__half2*)&st.x = __floats2half2_rn(acc.x, acc.y);
    *(__half2*)&st.y = __floats2half2_rn(acc.z, acc.w);
    *(uint2*)(agg + (size_t)node * 128 + lane * 4) = st;
}

// ---------------------------------------------------------------- gather2 + max-pool; norm on the fly
__global__ void k_gather64pool(const __half* __restrict__ h2,
                               const int* __restrict__ deg, const int* __restrict__ crow,
                               const float* __restrict__ dis, const float* __restrict__ b2,
                               const int* __restrict__ batch, float* __restrict__ pool)
{
    int node = (blockIdx.x * blockDim.x + threadIdx.x) >> 5;
    int lane = threadIdx.x & 31;
    if (node >= N_NODES) return;

    float dnode = dis[node];
    float dd = dnode * dnode;
    float2 acc = __half22float2(*(const __half2*)(h2 + (size_t)node * 64 + lane * 2));
    acc.x *= dd; acc.y *= dd;

    const int* base = crow + (size_t)node * CAP;
    int e = deg[node];
    int j = 0;
    for (; j + 7 < e; j += 8) {
        int p[8];
#pragma unroll
        for (int q = 0; q < 8; q++) p[q] = __ldg(base + j + q);
        float2 v[8];
        float nn[8];
#pragma unroll
        for (int q = 0; q < 8; q++) {
            v[q] = __half22float2(*(const __half2*)(h2 + (size_t)p[q] * 64 + lane * 2));
            nn[q] = __ldg(&dis[p[q]]) * dnode;
        }
#pragma unroll
        for (int q = 0; q < 8; q++) {
            acc.x = fmaf(v[q].x, nn[q], acc.x); acc.y = fmaf(v[q].y, nn[q], acc.y);
        }
    }
    for (; j + 3 < e; j += 4) {
        int p[4];
#pragma unroll
        for (int q = 0; q < 4; q++) p[q] = __ldg(base + j + q);
#pragma unroll
        for (int q = 0; q < 4; q++) {
            float2 v = __half22float2(*(const __half2*)(h2 + (size_t)p[q] * 64 + lane * 2));
            float n = __ldg(&dis[p[q]]) * dnode;
            acc.x = fmaf(v.x, n, acc.x); acc.y = fmaf(v.y, n, acc.y);
        }
    }
    for (; j < e; j++) {
        int p = __ldg(base + j);
        float n = __ldg(&dis[p]) * dnode;
        float2 v = __half22float2(*(const __half2*)(h2 + (size_t)p * 64 + lane * 2));
        acc.x = fmaf(v.x, n, acc.x); acc.y = fmaf(v.y, n, acc.y);
    }
    float2 bb = *(const float2*)(b2 + lane * 2);
    acc.x = fmaxf(acc.x + bb.x, 0.f);
    acc.y = fmaxf(acc.y + bb.y, 0.f);

    int gph = batch[node];
    atomicMax((unsigned int*)&pool[gph * H2 + lane * 2],     __float_as_uint(acc.x));
    atomicMax((unsigned int*)&pool[gph * H2 + lane * 2 + 1], __float_as_uint(acc.y));
}

// ---------------------------------------------------------------- final FC (re-zeroes pool after use)
__global__ void k_fc(float* __restrict__ pool, const float* __restrict__ Wfc,
                     const float* __restrict__ bfc, float* __restrict__ out)
{
    __shared__ float w[H2 * OUT_DIM];
    __shared__ float bb[OUT_DIM];
    int tid = threadIdx.x;
    for (int i = tid; i < H2 * OUT_DIM; i += blockDim.x) w[i] = Wfc[i];
    if (tid < OUT_DIM) bb[tid] = bfc[tid];
    __syncthreads();
    if (tid < N_GRAPHS) {
        float acc[OUT_DIM];
#pragma unroll
        for (int j = 0; j < OUT_DIM; j++) acc[j] = bb[j];
        for (int k = 0; k < H2; k++) {
            float g = pool[tid * H2 + k];
#pragma unroll
            for (int j = 0; j < OUT_DIM; j++) acc[j] = fmaf(g, w[k * OUT_DIM + j], acc[j]);
        }
#pragma unroll
        for (int j = 0; j < OUT_DIM; j++) out[tid * OUT_DIM + j] = acc[j];
    }
    __syncthreads();
    for (int i = tid; i < N_GRAPHS * H2; i += blockDim.x) pool[i] = 0.f;
}

// ---------------------------------------------------------------- launch
extern "C" void kernel_launch(void* const* d_in, const int* in_sizes, int n_in,
                              void* d_out, int out_size)
{
    const float* x    = (const float*)d_in[0];
    const int*   ei   = (const int*)d_in[1];
    const int*   batch= (const int*)d_in[2];
    const float* W1   = (const float*)d_in[3];
    const float* b1   = (const float*)d_in[4];
    const float* W2   = (const float*)d_in[5];
    const float* b2   = (const float*)d_in[6];
    const float* Wfc  = (const float*)d_in[7];
    const float* bfc  = (const float*)d_in[8];
    float* out = (float*)d_out;

    const int* row = ei;
    const int* col = ei + N_EDGES;

    int *cnt, *deg, *crow;
    float *dis, *pool;
    __half *h1, *agg1, *h2, *W1h, *W2h;
    cudaGetSymbolAddress((void**)&cnt,  g_cnt);
    cudaGetSymbolAddress((void**)&deg,  g_deg);
    cudaGetSymbolAddress((void**)&dis,  g_dis);
    cudaGetSymbolAddress((void**)&crow, g_crow);
    cudaGetSymbolAddress((void**)&W1h,  g_W1h);
    cudaGetSymbolAddress((void**)&W2h,  g_W2h);
    cudaGetSymbolAddress((void**)&h1,   g_h1);
    cudaGetSymbolAddress((void**)&agg1, g_agg1);
    cudaGetSymbolAddress((void**)&h2,   g_h2);
    cudaGetSymbolAddress((void**)&pool, g_pool);

    cudaFuncSetAttribute(k_gemm2_f16,
                         cudaFuncAttributeMaxDynamicSharedMemorySize, G2_SMEM);

    cudaStream_t s2;
    cudaStreamCreateWithFlags(&s2, cudaStreamNonBlocking);
    cudaEvent_t evF, evP, evJ;
    cudaEventCreateWithFlags(&evF, cudaEventDisableTiming);
    cudaEventCreateWithFlags(&evP, cudaEventDisableTiming);
    cudaEventCreateWithFlags(&evJ, cudaEventDisableTiming);

    // side: weight prep (tiny) -> evP; then fill + dis -> evJ
    cudaEventRecord(evF, 0);
    cudaStreamWaitEvent(s2, evF, 0);
    k_prepW<<<(IN_DIM * H1 + 255) / 256, 256, 0, s2>>>(W1, W2, W1h, W2h);
    cudaEventRecord(evP, s2);
    k_fill<<<(N_EDGES / 4 + 255) / 256, 256, 0, s2>>>(row, col, cnt, crow);
    k_dis<<<(N_NODES + 255) / 256, 256, 0, s2>>>(cnt, deg, dis);
    cudaEventRecord(evJ, s2);

    // main: GEMM1 (fp16) after W1h ready
    cudaStreamWaitEvent(0, evP, 0);
    k_gemm1_f16<<<(N_NODES + 127) / 128, 512>>>(x, W1h, h1, N_NODES);

    // join; gather1 (+b1+relu) -> agg1
    cudaStreamWaitEvent(0, evJ, 0);
    k_gather128<<<(N_NODES * 32 + 255) / 256, 256>>>(h1, agg1, deg, crow, dis, b1);

    // GEMM2
    k_gemm2_f16<<<(N_NODES + 127) / 128, 256, G2_SMEM>>>(agg1, W2h, h2, N_NODES);

    // gather2 + pool, FC
    k_gather64pool<<<(N_NODES * 32 + 255) / 256, 256>>>(h2, deg, crow, dis, b2, batch, pool);
    k_fc<<<1, 128>>>(pool, Wfc, bfc, out);
}